// round 3
// baseline (speedup 1.0000x reference)
#include <cuda_runtime.h>
#include <cuda_bf16.h>
#include <cstdint>

// ============================================================================
// LatentQuantizer: VQ codebook quantization.
// bf16 mma.sync (HMMA) distance GEMM -> distributed top-4 -> exact fp32 refine
// (+ full-fp32 fallback for margin-ambiguous rows).
// Inputs: latents [N*64] f32, scaler [N] f32, redshift [N] f32,
//         codebook_weight [64*1024] f32 (D-major).
// Output f32: z_q_st [N*64], scaler [N], redshift [N], loss [1], ids [N]
// ============================================================================

#define DIMS   64
#define NEMB   1024
#define MTILE  256          // rows per CTA
#define TPB    256          // 8 warps, 32 rows/warp

// dynamic smem layout (bytes)
#define SM_B     0                         // 1024 x 128B (bf16, swizzled)
#define SM_A     (SM_B + NEMB * 128)       // 131072: 256 x 128B
#define SM_WN    (SM_A + MTILE * 128)      // 163840: 1024 f32
#define SM_CAND  (SM_WN + NEMB * 4)        // 167936: 256 rows x 6 ints
#define SM_TOTAL (SM_CAND + MTILE * 6 * 4) // 174080

#define FB_CAP (1 << 19)

// -------------------- device scratch (no allocations) -----------------------
__device__ __align__(16)   float         g_Wtf[NEMB * DIMS];  // e-major fp32
__device__ __align__(1024) __nv_bfloat16 g_Wtb[NEMB * DIMS];  // e-major bf16, swizzled
__device__ float  g_wnorm[NEMB];
__device__ int    g_wmaxbits;
__device__ double g_loss;
__device__ int    g_nfb;
__device__ int    g_fbrows[FB_CAP];

// swizzle: 16B chunk kb within a 128B row -> kb ^ (row & 7)
__device__ __forceinline__ uint32_t sw128(uint32_t o) { return o ^ ((o >> 3) & 0x70); }

__device__ __forceinline__ uint32_t smem_u32(const void* p) {
    uint32_t a;
    asm("{ .reg .u64 t; cvta.to.shared.u64 t, %1; cvt.u32.u64 %0, t; }"
        : "=r"(a) : "l"(p));
    return a;
}

#define LDSM_X4(r, addr)                                                     \
    asm volatile("ldmatrix.sync.aligned.m8n8.x4.shared.b16 {%0,%1,%2,%3}, [%4];" \
        : "=r"((r)[0]), "=r"((r)[1]), "=r"((r)[2]), "=r"((r)[3])             \
        : "r"(addr))

__device__ __forceinline__ void mma16816(float* d, const uint32_t* a,
                                         const uint32_t* b) {
    asm volatile(
        "mma.sync.aligned.m16n8k16.row.col.f32.bf16.bf16.f32 "
        "{%0,%1,%2,%3}, {%4,%5,%6,%7}, {%8,%9}, {%0,%1,%2,%3};"
        : "+f"(d[0]), "+f"(d[1]), "+f"(d[2]), "+f"(d[3])
        : "r"(a[0]), "r"(a[1]), "r"(a[2]), "r"(a[3]), "r"(b[0]), "r"(b[1]));
}

// top-4 insert, strict < (stream visits e ascending -> first-index ties kept)
__device__ __forceinline__ void upd(float (&v)[4], int (&ix)[4], float s, int e) {
    if (s < v[3]) {
        if (s < v[2]) {
            v[3] = v[2]; ix[3] = ix[2];
            if (s < v[1]) {
                v[2] = v[1]; ix[2] = ix[1];
                if (s < v[0]) { v[1] = v[0]; ix[1] = ix[0]; v[0] = s; ix[0] = e; }
                else          { v[1] = s; ix[1] = e; }
            } else            { v[2] = s; ix[2] = e; }
        } else                { v[3] = s; ix[3] = e; }
    }
}
// tie-aware insert for cross-lane merge (prefer smaller index on equal value)
__device__ __forceinline__ void updm(float (&v)[4], int (&ix)[4], float s, int e) {
    if ((s < v[3]) || (s == v[3] && e < ix[3])) {
        if ((s < v[2]) || (s == v[2] && e < ix[2])) {
            v[3] = v[2]; ix[3] = ix[2];
            if ((s < v[1]) || (s == v[1] && e < ix[1])) {
                v[2] = v[1]; ix[2] = ix[1];
                if ((s < v[0]) || (s == v[0] && e < ix[0])) {
                    v[1] = v[0]; ix[1] = ix[0]; v[0] = s; ix[0] = e;
                } else { v[1] = s; ix[1] = e; }
            } else   { v[2] = s; ix[2] = e; }
        } else       { v[3] = s; ix[3] = e; }
    }
}

// ============================================================================
// prep: wnorm, wmax, fp32 transpose, swizzled bf16 transpose, zero accums
// ============================================================================
__global__ void prep_kernel(const float* __restrict__ W) {
    int e = blockIdx.x * blockDim.x + threadIdx.x;
    if (blockIdx.x == 0 && threadIdx.x == 0) { g_loss = 0.0; g_nfb = 0; }
    if (e >= NEMB) return;
    float col[DIMS];
    float s = 0.f;
    #pragma unroll
    for (int d = 0; d < DIMS; ++d) {
        float v = W[d * NEMB + e];          // coalesced across e
        col[d] = v;
        s = fmaf(v, v, s);
    }
    g_wnorm[e] = s;
    atomicMax(&g_wmaxbits, __float_as_int(s));   // s > 0 -> int-bit max valid
    float4* dst = (float4*)(g_Wtf + (size_t)e * DIMS);
    #pragma unroll
    for (int i = 0; i < DIMS / 4; ++i)
        dst[i] = make_float4(col[4*i], col[4*i+1], col[4*i+2], col[4*i+3]);
    char* bb = (char*)g_Wtb;
    #pragma unroll
    for (int k = 0; k < DIMS; k += 2) {
        __nv_bfloat162 p = __floats2bfloat162_rn(col[k], col[k + 1]);
        uint32_t bo = (uint32_t)e * 128u + (uint32_t)k * 2u;
        *(uint32_t*)(bb + sw128(bo)) = *(uint32_t*)&p;
    }
}

// ============================================================================
// vq: 256 rows/CTA. HMMA distances -> per-quad top-4 -> merge -> exact refine
// ============================================================================
__global__ __launch_bounds__(TPB, 1) void vq_kernel(
    const float* __restrict__ latents,
    const float* __restrict__ scaler,
    const float* __restrict__ redshift,
    float* __restrict__ out,
    int N)
{
    extern __shared__ char smem[];
    const uint32_t sb = smem_u32(smem);
    const int tid = threadIdx.x, wid = tid >> 5, lane = tid & 31;
    const long long row0 = (long long)blockIdx.x * MTILE;

    // ---- fill smem: B (raw copy, pre-swizzled), wnorm, A (f32->bf16 swizzled)
    {
        const float4* src = (const float4*)g_Wtb;
        float4* dst = (float4*)(smem + SM_B);
        #pragma unroll 8
        for (int i = tid; i < NEMB * 128 / 16; i += TPB) dst[i] = src[i];
    }
    float* swn = (float*)(smem + SM_WN);
    for (int i = tid; i < NEMB; i += TPB) swn[i] = g_wnorm[i];
    for (int i = tid; i < MTILE * 32; i += TPB) {       // 32 f32-pairs per row
        int r = i >> 5, kp = i & 31;
        long long gr = row0 + r;
        float2 z2 = (gr < N) ? ((const float2*)latents)[gr * 32 + kp]
                             : make_float2(0.f, 0.f);
        __nv_bfloat162 p = __floats2bfloat162_rn(z2.x, z2.y);
        *(uint32_t*)(smem + SM_A + sw128((uint32_t)r * 128u + (uint32_t)kp * 4u))
            = *(uint32_t*)&p;
    }
    __syncthreads();

    // ---- A fragments (register resident): 2 m16 tiles x 4 k16 steps
    const int wb = wid * 32;
    uint32_t afrag[2][4][4];
    {
        int row = wb + ((lane >> 3) & 1) * 8 + (lane & 7);
        #pragma unroll
        for (int mt = 0; mt < 2; ++mt) {
            int rr = row + mt * 16;
            #pragma unroll
            for (int ks = 0; ks < 4; ++ks) {
                int kb = ks * 2 + (lane >> 4);
                uint32_t ad = sb + SM_A + rr * 128 + ((kb ^ (rr & 7)) << 4);
                LDSM_X4(afrag[mt][ks], ad);
            }
        }
    }

    // ---- B ldmatrix per-lane address components (n0 added in loop)
    const uint32_t brow = sb + SM_B + (lane & 7) * 128;
    const uint32_t bx1  = (((lane >> 3) ^ (lane & 7)) << 4);        // kb 0..3
    const uint32_t bx2  = ((((lane >> 3) + 4) ^ (lane & 7)) << 4);  // kb 4..7

    float tv[4][4];
    int   ti[4][4];
    #pragma unroll
    for (int st = 0; st < 4; ++st)
        #pragma unroll
        for (int k = 0; k < 4; ++k) { tv[st][k] = 3.402823466e38f; ti[st][k] = k; }

    const int cbase = (lane & 3) * 2;
    #pragma unroll 2
    for (int nt = 0; nt < NEMB / 8; ++nt) {
        const int n0 = nt * 8;
        uint32_t b[8];
        LDSM_X4(b,     brow + n0 * 128 + bx1);
        LDSM_X4(b + 4, brow + n0 * 128 + bx2);
        float d0[4] = {0.f, 0.f, 0.f, 0.f};
        float d1[4] = {0.f, 0.f, 0.f, 0.f};
        #pragma unroll
        for (int ks = 0; ks < 4; ++ks) {
            mma16816(d0, afrag[0][ks], b + 2 * ks);
            mma16816(d1, afrag[1][ks], b + 2 * ks);
        }
        const int c0 = n0 + cbase, c1 = c0 + 1;
        const float wn0 = swn[c0], wn1 = swn[c1];
        upd(tv[0], ti[0], fmaf(d0[0], -2.f, wn0), c0);
        upd(tv[0], ti[0], fmaf(d0[1], -2.f, wn1), c1);
        upd(tv[1], ti[1], fmaf(d0[2], -2.f, wn0), c0);
        upd(tv[1], ti[1], fmaf(d0[3], -2.f, wn1), c1);
        upd(tv[2], ti[2], fmaf(d1[0], -2.f, wn0), c0);
        upd(tv[2], ti[2], fmaf(d1[1], -2.f, wn1), c1);
        upd(tv[3], ti[3], fmaf(d1[2], -2.f, wn0), c0);
        upd(tv[3], ti[3], fmaf(d1[3], -2.f, wn1), c1);
    }

    // ---- merge top-4 across the 4 lanes sharing each row (butterfly)
    #pragma unroll
    for (int st = 0; st < 4; ++st) {
        #pragma unroll
        for (int m = 1; m <= 2; m <<= 1) {
            float u[4]; int j[4];
            #pragma unroll
            for (int k = 0; k < 4; ++k) {
                u[k] = __shfl_xor_sync(0xffffffffu, tv[st][k], m);
                j[k] = __shfl_xor_sync(0xffffffffu, ti[st][k], m);
            }
            #pragma unroll
            for (int k = 0; k < 4; ++k) updm(tv[st], ti[st], u[k], j[k]);
        }
    }

    // ---- publish candidates per row, redistribute 1 row/thread
    int* scand = (int*)(smem + SM_CAND);
    if ((lane & 3) == 0) {
        int q = lane >> 2;
        #pragma unroll
        for (int st = 0; st < 4; ++st) {
            int rl = wb + q + (st & 1) * 8 + (st >> 1) * 16;
            int* cp = scand + rl * 6;
            cp[0] = ti[st][0]; cp[1] = ti[st][1];
            cp[2] = ti[st][2]; cp[3] = ti[st][3];
            cp[4] = __float_as_int(tv[st][0]);
            cp[5] = __float_as_int(tv[st][3]);
        }
    }
    __syncwarp();

    // ---- exact fp32 refine of top-4 + epilogue (one row per thread)
    const int rl = wb + lane;
    const long long r = row0 + rl;
    float lsum = 0.f;
    if (r < N) {
        const int* cp = scand + rl * 6;
        const int i0 = cp[0], i1 = cp[1], i2 = cp[2], i3 = cp[3];
        const float av0 = __int_as_float(cp[4]), av3 = __int_as_float(cp[5]);
        const float4* zr = (const float4*)(latents + r * DIMS);
        const float4* w0 = (const float4*)(g_Wtf + (size_t)i0 * DIMS);
        const float4* w1 = (const float4*)(g_Wtf + (size_t)i1 * DIMS);
        const float4* w2 = (const float4*)(g_Wtf + (size_t)i2 * DIMS);
        const float4* w3 = (const float4*)(g_Wtf + (size_t)i3 * DIMS);
        float a0 = 0.f, a1 = 0.f, a2 = 0.f, a3 = 0.f, zn = 0.f;
        #pragma unroll
        for (int i = 0; i < DIMS / 4; ++i) {
            float4 z = zr[i];
            zn = fmaf(z.x, z.x, zn); zn = fmaf(z.y, z.y, zn);
            zn = fmaf(z.z, z.z, zn); zn = fmaf(z.w, z.w, zn);
            float4 p;
            p = w0[i]; a0 = fmaf(z.x,p.x,a0); a0 = fmaf(z.y,p.y,a0); a0 = fmaf(z.z,p.z,a0); a0 = fmaf(z.w,p.w,a0);
            p = w1[i]; a1 = fmaf(z.x,p.x,a1); a1 = fmaf(z.y,p.y,a1); a1 = fmaf(z.z,p.z,a1); a1 = fmaf(z.w,p.w,a1);
            p = w2[i]; a2 = fmaf(z.x,p.x,a2); a2 = fmaf(z.y,p.y,a2); a2 = fmaf(z.z,p.z,a2); a2 = fmaf(z.w,p.w,a2);
            p = w3[i]; a3 = fmaf(z.x,p.x,a3); a3 = fmaf(z.y,p.y,a3); a3 = fmaf(z.z,p.z,a3); a3 = fmaf(z.w,p.w,a3);
        }
        // completeness margin: |s~ - s| <= 2 * 2^-7 * ||z|| * max||w||
        float wmax = __int_as_float(g_wmaxbits);
        float margin = 0.03125f * sqrtf(wmax) * sqrtf(zn) + 1e-3f;
        if ((av3 - av0) < margin) {
            int ix = atomicAdd(&g_nfb, 1);
            if (ix < FB_CAP) g_fbrows[ix] = (int)r;
        } else {
            // exact reference association order: (zn - 2*dot) + wnorm
            float e0 = (zn - 2.f * a0) + swn[i0];
            float e1 = (zn - 2.f * a1) + swn[i1];
            float e2 = (zn - 2.f * a2) + swn[i2];
            float e3 = (zn - 2.f * a3) + swn[i3];
            float bd = e0; int be = i0;
            if (e1 < bd || (e1 == bd && i1 < be)) { bd = e1; be = i1; }
            if (e2 < bd || (e2 == bd && i2 < be)) { bd = e2; be = i2; }
            if (e3 < bd || (e3 == bd && i3 < be)) { bd = e3; be = i3; }
            const float4* wq = (const float4*)(g_Wtf + (size_t)be * DIMS);
            float4* oz = (float4*)(out + r * DIMS);
            #pragma unroll
            for (int i = 0; i < DIMS / 4; ++i) {
                float4 z = zr[i], w = wq[i];
                float q0 = w.x - z.x, q1 = w.y - z.y, q2 = w.z - z.z, q3 = w.w - z.w;
                lsum += q0*q0 + q1*q1 + q2*q2 + q3*q3;
                oz[i] = make_float4(z.x + q0, z.y + q1, z.z + q2, z.w + q3);
            }
            out[(long long)N * DIMS + 2LL * N + 1 + r] = (float)be;  // ids
        }
        out[(long long)N * DIMS + r]     = scaler[r];
        out[(long long)N * DIMS + N + r] = redshift[r];
    }

    // ---- block loss reduction
    #pragma unroll
    for (int o = 16; o > 0; o >>= 1)
        lsum += __shfl_down_sync(0xffffffffu, lsum, o);
    __shared__ float wsum[TPB / 32];
    if (lane == 0) wsum[wid] = lsum;
    __syncthreads();
    if (tid == 0) {
        float t = 0.f;
        #pragma unroll
        for (int w = 0; w < TPB / 32; ++w) t += wsum[w];
        atomicAdd(&g_loss, (double)t);
    }
}

// ============================================================================
// fallback: exact fp32 full scan for ambiguous rows (one warp per row)
// ============================================================================
__global__ void fb_kernel(const float* __restrict__ latents,
                          float* __restrict__ out, int N)
{
    __shared__ float zbuf[4][DIMS];
    const int lane = threadIdx.x & 31, w = threadIdx.x >> 5;
    const int warps = (gridDim.x * blockDim.x) >> 5;
    const int gw = (blockIdx.x * blockDim.x + threadIdx.x) >> 5;
    const int nfb = min(g_nfb, FB_CAP);

    for (int i = gw; i < nfb; i += warps) {
        const long long row = g_fbrows[i];
        zbuf[w][2*lane]     = latents[row * DIMS + 2*lane];
        zbuf[w][2*lane + 1] = latents[row * DIMS + 2*lane + 1];
        __syncwarp();
        float zp = zbuf[w][2*lane] * zbuf[w][2*lane]
                 + zbuf[w][2*lane+1] * zbuf[w][2*lane+1];
        #pragma unroll
        for (int o = 16; o > 0; o >>= 1) zp += __shfl_down_sync(0xffffffffu, zp, o);
        float zn = __shfl_sync(0xffffffffu, zp, 0);

        const float4* z4 = (const float4*)zbuf[w];
        float bd = 3.4e38f; int be = NEMB;
        for (int e = lane; e < NEMB; e += 32) {
            const float4* wp = (const float4*)(g_Wtf + (size_t)e * DIMS);
            float a = 0.f;
            #pragma unroll
            for (int k = 0; k < DIMS / 4; ++k) {
                float4 z = z4[k], p = wp[k];
                a = fmaf(z.x,p.x,a); a = fmaf(z.y,p.y,a);
                a = fmaf(z.z,p.z,a); a = fmaf(z.w,p.w,a);
            }
            float d = (zn - 2.f * a) + g_wnorm[e];
            if (d < bd || (d == bd && e < be)) { bd = d; be = e; }
        }
        #pragma unroll
        for (int o = 16; o > 0; o >>= 1) {
            float od = __shfl_down_sync(0xffffffffu, bd, o);
            int   oe = __shfl_down_sync(0xffffffffu, be, o);
            if (od < bd || (od == bd && oe < be)) { bd = od; be = oe; }
        }
        be = __shfl_sync(0xffffffffu, be, 0);

        float l = 0.f;
        #pragma unroll
        for (int k = 0; k < 2; ++k) {
            int d = 2*lane + k;
            float z = zbuf[w][d];
            float wv = g_Wtf[(size_t)be * DIMS + d];
            float df = wv - z;
            l += df * df;
            out[row * DIMS + d] = z + df;
        }
        #pragma unroll
        for (int o = 16; o > 0; o >>= 1) l += __shfl_down_sync(0xffffffffu, l, o);
        if (lane == 0) {
            atomicAdd(&g_loss, (double)l);
            out[(long long)N * DIMS + 2LL * N + 1 + row] = (float)be;
        }
        __syncwarp();
    }
}

__global__ void finalize_kernel(float* __restrict__ out, long long off, double scale) {
    out[off] = (float)(g_loss * scale);
}

// ============================================================================
extern "C" void kernel_launch(void* const* d_in, const int* in_sizes, int n_in,
                              void* d_out, int out_size) {
    const float* latents  = (const float*)d_in[0];
    const float* scaler   = (const float*)d_in[1];
    const float* redshift = (const float*)d_in[2];
    const float* W        = (const float*)d_in[3];
    float* out = (float*)d_out;
    const int N = in_sizes[1];

    cudaFuncSetAttribute(vq_kernel, cudaFuncAttributeMaxDynamicSharedMemorySize,
                         SM_TOTAL);

    prep_kernel<<<(NEMB + 255) / 256, 256>>>(W);
    vq_kernel<<<(N + MTILE - 1) / MTILE, TPB, SM_TOTAL>>>(latents, scaler,
                                                          redshift, out, N);
    fb_kernel<<<256, 128>>>(latents, out, N);
    finalize_kernel<<<1, 1>>>(out, (long long)N * DIMS + 2LL * N,
                              1.25 / ((double)N * (double)DIMS));
}

// round 4
// speedup vs baseline: 1.6337x; 1.6337x over previous
#include <cuda_runtime.h>
#include <cuda_bf16.h>
#include <cstdint>

// ============================================================================
// LatentQuantizer: bf16 HMMA distance GEMM -> per-lane top-8 -> tiered exact
// fp32 refine (top-4 / top-8) -> rare full-fp32 fallback.
// Inputs: latents [N*64] f32, scaler [N] f32, redshift [N] f32,
//         codebook_weight [64*1024] f32 (D-major).
// Output f32: z_q_st [N*64], scaler [N], redshift [N], loss [1], ids [N]
// ============================================================================

#define DIMS   64
#define NEMB   1024
#define MTILE  256          // rows per CTA
#define TPB    256          // 8 warps, 32 rows/warp
#define TOPK   8

// dynamic smem layout (bytes)
#define SM_B     0                          // 1024 x 128B (bf16, swizzled)
#define SM_A     (SM_B + NEMB * 128)        // 131072: 256 x 128B
#define SM_WN    (SM_A + MTILE * 128)       // 163840: 1024 f32
#define SM_CAND  (SM_WN + NEMB * 4)         // 167936: 256 rows x 12 ints
#define SM_TOTAL (SM_CAND + MTILE * 12 * 4) // 180224

#define FB_CAP (1 << 19)

// -------------------- device scratch (no allocations) -----------------------
__device__ __align__(16)   float         g_Wtf[NEMB * DIMS];  // e-major fp32
__device__ __align__(1024) __nv_bfloat16 g_Wtb[NEMB * DIMS];  // e-major bf16, swizzled
__device__ float  g_wnorm[NEMB];
__device__ int    g_wmaxbits;
__device__ double g_loss;
__device__ int    g_nfb;
__device__ int    g_fbrows[FB_CAP];

__device__ __forceinline__ uint32_t sw128(uint32_t o) { return o ^ ((o >> 3) & 0x70); }

__device__ __forceinline__ uint32_t smem_u32(const void* p) {
    uint32_t a;
    asm("{ .reg .u64 t; cvta.to.shared.u64 t, %1; cvt.u32.u64 %0, t; }"
        : "=r"(a) : "l"(p));
    return a;
}

#define LDSM_X4(r, addr)                                                     \
    asm volatile("ldmatrix.sync.aligned.m8n8.x4.shared.b16 {%0,%1,%2,%3}, [%4];" \
        : "=r"((r)[0]), "=r"((r)[1]), "=r"((r)[2]), "=r"((r)[3])             \
        : "r"(addr))

__device__ __forceinline__ void mma16816(float* d, const uint32_t* a,
                                         const uint32_t* b) {
    asm volatile(
        "mma.sync.aligned.m16n8k16.row.col.f32.bf16.bf16.f32 "
        "{%0,%1,%2,%3}, {%4,%5,%6,%7}, {%8,%9}, {%0,%1,%2,%3};"
        : "+f"(d[0]), "+f"(d[1]), "+f"(d[2]), "+f"(d[3])
        : "r"(a[0]), "r"(a[1]), "r"(a[2]), "r"(a[3]), "r"(b[0]), "r"(b[1]));
}

// stream insert into sorted top-8 (ascending e order -> strict < keeps first
// index on ties). Entry gate is the only cost on the common path.
__device__ __forceinline__ void upd8(float (&v)[TOPK], int (&ix)[TOPK],
                                     float s, int e) {
    if (s < v[TOPK - 1]) {
        v[TOPK - 1] = s; ix[TOPK - 1] = e;
        #pragma unroll
        for (int k = TOPK - 1; k > 0; --k) {
            bool sw = v[k] < v[k - 1];        // equal -> no swap (earlier e wins)
            float fv = sw ? v[k] : v[k - 1];
            int   fi = sw ? ix[k] : ix[k - 1];
            float gv = sw ? v[k - 1] : v[k];
            int   gi = sw ? ix[k - 1] : ix[k];
            v[k - 1] = fv; ix[k - 1] = fi;
            v[k]     = gv; ix[k]     = gi;
        }
    }
}
// tie-aware insert for cross-lane merge (prefer smaller index on equal value)
__device__ __forceinline__ void updm8(float (&v)[TOPK], int (&ix)[TOPK],
                                      float s, int e) {
    if (s < v[TOPK - 1] || (s == v[TOPK - 1] && e < ix[TOPK - 1])) {
        v[TOPK - 1] = s; ix[TOPK - 1] = e;
        #pragma unroll
        for (int k = TOPK - 1; k > 0; --k) {
            bool sw = (v[k] < v[k - 1]) || (v[k] == v[k - 1] && ix[k] < ix[k - 1]);
            float fv = sw ? v[k] : v[k - 1];
            int   fi = sw ? ix[k] : ix[k - 1];
            float gv = sw ? v[k - 1] : v[k];
            int   gi = sw ? ix[k - 1] : ix[k];
            v[k - 1] = fv; ix[k - 1] = fi;
            v[k]     = gv; ix[k]     = gi;
        }
    }
}

// ============================================================================
// prep
// ============================================================================
__global__ void prep_kernel(const float* __restrict__ W) {
    int e = blockIdx.x * blockDim.x + threadIdx.x;
    if (blockIdx.x == 0 && threadIdx.x == 0) { g_loss = 0.0; g_nfb = 0; }
    if (e >= NEMB) return;
    float col[DIMS];
    float s = 0.f;
    #pragma unroll
    for (int d = 0; d < DIMS; ++d) {
        float v = W[d * NEMB + e];
        col[d] = v;
        s = fmaf(v, v, s);
    }
    g_wnorm[e] = s;
    atomicMax(&g_wmaxbits, __float_as_int(s));
    float4* dst = (float4*)(g_Wtf + (size_t)e * DIMS);
    #pragma unroll
    for (int i = 0; i < DIMS / 4; ++i)
        dst[i] = make_float4(col[4*i], col[4*i+1], col[4*i+2], col[4*i+3]);
    char* bb = (char*)g_Wtb;
    #pragma unroll
    for (int k = 0; k < DIMS; k += 2) {
        __nv_bfloat162 p = __floats2bfloat162_rn(col[k], col[k + 1]);
        uint32_t bo = (uint32_t)e * 128u + (uint32_t)k * 2u;
        *(uint32_t*)(bb + sw128(bo)) = *(uint32_t*)&p;
    }
}

// ============================================================================
// vq
// ============================================================================
__global__ __launch_bounds__(TPB, 1) void vq_kernel(
    const float* __restrict__ latents,
    const float* __restrict__ scaler,
    const float* __restrict__ redshift,
    float* __restrict__ out,
    int N)
{
    extern __shared__ char smem[];
    const uint32_t sb = smem_u32(smem);
    const int tid = threadIdx.x, wid = tid >> 5, lane = tid & 31;
    const long long row0 = (long long)blockIdx.x * MTILE;

    // ---- fill smem
    {
        const float4* src = (const float4*)g_Wtb;
        float4* dst = (float4*)(smem + SM_B);
        #pragma unroll 8
        for (int i = tid; i < NEMB * 128 / 16; i += TPB) dst[i] = src[i];
    }
    float* swn = (float*)(smem + SM_WN);
    for (int i = tid; i < NEMB; i += TPB) swn[i] = g_wnorm[i];
    for (int i = tid; i < MTILE * 32; i += TPB) {
        int r = i >> 5, kp = i & 31;
        long long gr = row0 + r;
        float2 z2 = (gr < N) ? ((const float2*)latents)[gr * 32 + kp]
                             : make_float2(0.f, 0.f);
        __nv_bfloat162 p = __floats2bfloat162_rn(z2.x, z2.y);
        *(uint32_t*)(smem + SM_A + sw128((uint32_t)r * 128u + (uint32_t)kp * 4u))
            = *(uint32_t*)&p;
    }
    __syncthreads();

    // ---- A fragments (register resident): 2 m16 tiles x 4 k16 steps
    const int wb = wid * 32;
    uint32_t afrag[2][4][4];
    {
        int row = wb + ((lane >> 3) & 1) * 8 + (lane & 7);
        #pragma unroll
        for (int mt = 0; mt < 2; ++mt) {
            int rr = row + mt * 16;
            #pragma unroll
            for (int ks = 0; ks < 4; ++ks) {
                int kb = ks * 2 + (lane >> 4);
                uint32_t ad = sb + SM_A + rr * 128 + ((kb ^ (rr & 7)) << 4);
                LDSM_X4(afrag[mt][ks], ad);
            }
        }
    }

    const uint32_t brow = sb + SM_B + (lane & 7) * 128;
    const uint32_t bx1  = (((lane >> 3) ^ (lane & 7)) << 4);
    const uint32_t bx2  = ((((lane >> 3) + 4) ^ (lane & 7)) << 4);

    float tv[4][TOPK];
    int   ti[4][TOPK];
    #pragma unroll
    for (int st = 0; st < 4; ++st)
        #pragma unroll
        for (int k = 0; k < TOPK; ++k) { tv[st][k] = 3.402823466e38f; ti[st][k] = k; }

    const int cbase = (lane & 3) * 2;
    #pragma unroll 2
    for (int nt = 0; nt < NEMB / 8; ++nt) {
        const int n0 = nt * 8;
        uint32_t b[8];
        LDSM_X4(b,     brow + n0 * 128 + bx1);
        LDSM_X4(b + 4, brow + n0 * 128 + bx2);
        float d0[4] = {0.f, 0.f, 0.f, 0.f};
        float d1[4] = {0.f, 0.f, 0.f, 0.f};
        #pragma unroll
        for (int ks = 0; ks < 4; ++ks) {
            mma16816(d0, afrag[0][ks], b + 2 * ks);
            mma16816(d1, afrag[1][ks], b + 2 * ks);
        }
        const int c0 = n0 + cbase, c1 = c0 + 1;
        const float wn0 = swn[c0], wn1 = swn[c1];
        upd8(tv[0], ti[0], fmaf(d0[0], -2.f, wn0), c0);
        upd8(tv[0], ti[0], fmaf(d0[1], -2.f, wn1), c1);
        upd8(tv[1], ti[1], fmaf(d0[2], -2.f, wn0), c0);
        upd8(tv[1], ti[1], fmaf(d0[3], -2.f, wn1), c1);
        upd8(tv[2], ti[2], fmaf(d1[0], -2.f, wn0), c0);
        upd8(tv[2], ti[2], fmaf(d1[1], -2.f, wn1), c1);
        upd8(tv[3], ti[3], fmaf(d1[2], -2.f, wn0), c0);
        upd8(tv[3], ti[3], fmaf(d1[3], -2.f, wn1), c1);
    }

    // ---- merge top-8 across the 4 lanes sharing each row (butterfly)
    #pragma unroll
    for (int st = 0; st < 4; ++st) {
        #pragma unroll
        for (int m = 1; m <= 2; m <<= 1) {
            float u[TOPK]; int j[TOPK];
            #pragma unroll
            for (int k = 0; k < TOPK; ++k) {
                u[k] = __shfl_xor_sync(0xffffffffu, tv[st][k], m);
                j[k] = __shfl_xor_sync(0xffffffffu, ti[st][k], m);
            }
            #pragma unroll
            for (int k = 0; k < TOPK; ++k) updm8(tv[st], ti[st], u[k], j[k]);
        }
    }

    // ---- publish candidates per row: 8 idx + v0/v3/v7 bits
    int* scand = (int*)(smem + SM_CAND);
    if ((lane & 3) == 0) {
        int q = lane >> 2;
        #pragma unroll
        for (int st = 0; st < 4; ++st) {
            int rl = wb + q + (st & 1) * 8 + (st >> 1) * 16;
            int* cp = scand + rl * 12;
            #pragma unroll
            for (int k = 0; k < TOPK; ++k) cp[k] = ti[st][k];
            cp[8]  = __float_as_int(tv[st][0]);
            cp[9]  = __float_as_int(tv[st][3]);
            cp[10] = __float_as_int(tv[st][7]);
        }
    }
    __syncwarp();

    // ---- tiered exact fp32 refine + epilogue (one row per thread)
    const int rl = wb + lane;
    const long long r = row0 + rl;
    float lsum = 0.f;
    if (r < N) {
        const int* cp = scand + rl * 12;
        const float av0 = __int_as_float(cp[8]);
        const float av3 = __int_as_float(cp[9]);
        const float av7 = __int_as_float(cp[10]);
        const float4* zr = (const float4*)(latents + r * DIMS);
        float zn = 0.f;
        float4 z[DIMS / 4];
        #pragma unroll
        for (int i = 0; i < DIMS / 4; ++i) {
            z[i] = zr[i];
            zn = fmaf(z[i].x, z[i].x, zn); zn = fmaf(z[i].y, z[i].y, zn);
            zn = fmaf(z[i].z, z[i].z, zn); zn = fmaf(z[i].w, z[i].w, zn);
        }
        // rigorous bf16 completeness margin: 2*eps = 2^-5 * ||z|| * max||w||
        float wmax = __int_as_float(g_wmaxbits);
        float margin = 0.03125f * sqrtf(zn * wmax) + 1e-4f;

        if (av7 - av0 < margin) {
            int ix = atomicAdd(&g_nfb, 1);
            if (ix < FB_CAP) g_fbrows[ix] = (int)r;
        } else {
            const int nc = (av3 - av0 >= margin) ? 4 : 8;
            float bd = 3.402823466e38f; int be = NEMB;
            #pragma unroll 4
            for (int c = 0; c < nc; ++c) {
                const int ie = cp[c];
                const float4* wp = (const float4*)(g_Wtf + (size_t)ie * DIMS);
                float a = 0.f;
                #pragma unroll
                for (int i = 0; i < DIMS / 4; ++i) {
                    float4 p = wp[i];
                    a = fmaf(z[i].x, p.x, a); a = fmaf(z[i].y, p.y, a);
                    a = fmaf(z[i].z, p.z, a); a = fmaf(z[i].w, p.w, a);
                }
                float d = (zn - 2.f * a) + swn[ie];  // exact reference order
                if (d < bd || (d == bd && ie < be)) { bd = d; be = ie; }
            }
            const float4* wq = (const float4*)(g_Wtf + (size_t)be * DIMS);
            float4* oz = (float4*)(out + r * DIMS);
            #pragma unroll
            for (int i = 0; i < DIMS / 4; ++i) {
                float4 w = wq[i];
                float q0 = w.x - z[i].x, q1 = w.y - z[i].y;
                float q2 = w.z - z[i].z, q3 = w.w - z[i].w;
                lsum += q0*q0 + q1*q1 + q2*q2 + q3*q3;
                oz[i] = make_float4(z[i].x + q0, z[i].y + q1,
                                    z[i].z + q2, z[i].w + q3);
            }
            out[(long long)N * DIMS + 2LL * N + 1 + r] = (float)be;
        }
        out[(long long)N * DIMS + r]     = scaler[r];
        out[(long long)N * DIMS + N + r] = redshift[r];
    }

    // ---- block loss reduction
    #pragma unroll
    for (int o = 16; o > 0; o >>= 1)
        lsum += __shfl_down_sync(0xffffffffu, lsum, o);
    __shared__ float wsum[TPB / 32];
    if (lane == 0) wsum[wid] = lsum;
    __syncthreads();
    if (tid == 0) {
        float t = 0.f;
        #pragma unroll
        for (int w = 0; w < TPB / 32; ++w) t += wsum[w];
        atomicAdd(&g_loss, (double)t);
    }
}

// ============================================================================
// fallback: exact fp32 full scan (one warp per row); expected ~1e-3 of rows
// ============================================================================
__global__ void fb_kernel(const float* __restrict__ latents,
                          float* __restrict__ out, int N)
{
    __shared__ float zbuf[4][DIMS];
    const int lane = threadIdx.x & 31, w = threadIdx.x >> 5;
    const int warps = (gridDim.x * blockDim.x) >> 5;
    const int gw = (blockIdx.x * blockDim.x + threadIdx.x) >> 5;
    const int nfb = min(g_nfb, FB_CAP);

    for (int i = gw; i < nfb; i += warps) {
        const long long row = g_fbrows[i];
        zbuf[w][2*lane]     = latents[row * DIMS + 2*lane];
        zbuf[w][2*lane + 1] = latents[row * DIMS + 2*lane + 1];
        __syncwarp();
        float zp = zbuf[w][2*lane] * zbuf[w][2*lane]
                 + zbuf[w][2*lane+1] * zbuf[w][2*lane+1];
        #pragma unroll
        for (int o = 16; o > 0; o >>= 1) zp += __shfl_down_sync(0xffffffffu, zp, o);
        float zn = __shfl_sync(0xffffffffu, zp, 0);

        const float4* z4 = (const float4*)zbuf[w];
        float bd = 3.4e38f; int be = NEMB;
        for (int e = lane; e < NEMB; e += 32) {
            const float4* wp = (const float4*)(g_Wtf + (size_t)e * DIMS);
            float a = 0.f;
            #pragma unroll
            for (int k = 0; k < DIMS / 4; ++k) {
                float4 zv = z4[k], p = wp[k];
                a = fmaf(zv.x,p.x,a); a = fmaf(zv.y,p.y,a);
                a = fmaf(zv.z,p.z,a); a = fmaf(zv.w,p.w,a);
            }
            float d = (zn - 2.f * a) + g_wnorm[e];
            if (d < bd || (d == bd && e < be)) { bd = d; be = e; }
        }
        #pragma unroll
        for (int o = 16; o > 0; o >>= 1) {
            float od = __shfl_down_sync(0xffffffffu, bd, o);
            int   oe = __shfl_down_sync(0xffffffffu, be, o);
            if (od < bd || (od == bd && oe < be)) { bd = od; be = oe; }
        }
        be = __shfl_sync(0xffffffffu, be, 0);

        float l = 0.f;
        #pragma unroll
        for (int k = 0; k < 2; ++k) {
            int d = 2*lane + k;
            float zv = zbuf[w][d];
            float wv = g_Wtf[(size_t)be * DIMS + d];
            float df = wv - zv;
            l += df * df;
            out[row * DIMS + d] = zv + df;
        }
        #pragma unroll
        for (int o = 16; o > 0; o >>= 1) l += __shfl_down_sync(0xffffffffu, l, o);
        if (lane == 0) {
            atomicAdd(&g_loss, (double)l);
            out[(long long)N * DIMS + 2LL * N + 1 + row] = (float)be;
        }
        __syncwarp();
    }
}

__global__ void finalize_kernel(float* __restrict__ out, long long off, double scale) {
    out[off] = (float)(g_loss * scale);
}

// ============================================================================
extern "C" void kernel_launch(void* const* d_in, const int* in_sizes, int n_in,
                              void* d_out, int out_size) {
    const float* latents  = (const float*)d_in[0];
    const float* scaler   = (const float*)d_in[1];
    const float* redshift = (const float*)d_in[2];
    const float* W        = (const float*)d_in[3];
    float* out = (float*)d_out;
    const int N = in_sizes[1];

    cudaFuncSetAttribute(vq_kernel, cudaFuncAttributeMaxDynamicSharedMemorySize,
                         SM_TOTAL);

    prep_kernel<<<(NEMB + 255) / 256, 256>>>(W);
    vq_kernel<<<(N + MTILE - 1) / MTILE, TPB, SM_TOTAL>>>(latents, scaler,
                                                          redshift, out, N);
    fb_kernel<<<256, 128>>>(latents, out, N);
    finalize_kernel<<<1, 1>>>(out, (long long)N * DIMS + 2LL * N,
                              1.25 / ((double)N * (double)DIMS));
}

// round 5
// speedup vs baseline: 3.9001x; 2.3873x over previous
#include <cuda_runtime.h>
#include <cuda_bf16.h>
#include <cstdint>

// ============================================================================
// LatentQuantizer: bf16 HMMA distance GEMM, two-pass (min, then threshold
// candidate collection) -> exact fp32 lexicographic refine -> rare fallback.
// Inputs: latents [N*64] f32, scaler [N] f32, redshift [N] f32,
//         codebook_weight [64*1024] f32 (D-major).
// Output f32: z_q_st [N*64], scaler [N], redshift [N], loss [1], ids [N]
// ============================================================================

#define DIMS   64
#define NEMB   1024
#define MTILE  512          // rows per CTA
#define TPB    512          // 16 warps, 32 rows/warp
#define NSLOT  12

// dynamic smem layout (bytes)
#define SM_B     0                           // 1024 x 128B bf16 swizzled
#define SM_A     (SM_B + NEMB * 128)         // 131072: 512 x 128B
#define SM_WN    (SM_A + MTILE * 128)        // 196608: 1024 f32
#define SM_ZN    (SM_WN + NEMB * 4)          // 200704: 512 f32
#define SM_CAND  (SM_ZN + MTILE * 4)         // 202752: 512 x NSLOT ints
#define SM_CNT   (SM_CAND + MTILE * NSLOT * 4) // 227328: 512 ints
#define SM_WSUM  (SM_CNT + MTILE * 4)        // 229376: 16 f32
#define SM_TOTAL (SM_WSUM + 64)              // 229440

#define FB_CAP (1 << 19)

// -------------------- device scratch (no allocations) -----------------------
__device__ __align__(16)   float         g_Wtf[NEMB * DIMS];  // e-major fp32
__device__ __align__(1024) __nv_bfloat16 g_Wtb[NEMB * DIMS];  // e-major bf16, swizzled
__device__ float  g_wnorm[NEMB];
__device__ int    g_wmaxbits;
__device__ double g_loss;
__device__ int    g_nfb;
__device__ int    g_fbrows[FB_CAP];

__device__ __forceinline__ uint32_t sw128(uint32_t o) { return o ^ ((o >> 3) & 0x70); }

__device__ __forceinline__ uint32_t smem_u32(const void* p) {
    uint32_t a;
    asm("{ .reg .u64 t; cvta.to.shared.u64 t, %1; cvt.u32.u64 %0, t; }"
        : "=r"(a) : "l"(p));
    return a;
}

#define LDSM_X4(r, addr)                                                     \
    asm volatile("ldmatrix.sync.aligned.m8n8.x4.shared.b16 {%0,%1,%2,%3}, [%4];" \
        : "=r"((r)[0]), "=r"((r)[1]), "=r"((r)[2]), "=r"((r)[3])             \
        : "r"(addr))

__device__ __forceinline__ void mma16816(float* d, const uint32_t* a,
                                         const uint32_t* b) {
    asm volatile(
        "mma.sync.aligned.m16n8k16.row.col.f32.bf16.bf16.f32 "
        "{%0,%1,%2,%3}, {%4,%5,%6,%7}, {%8,%9}, {%0,%1,%2,%3};"
        : "+f"(d[0]), "+f"(d[1]), "+f"(d[2]), "+f"(d[3])
        : "r"(a[0]), "r"(a[1]), "r"(a[2]), "r"(a[3]), "r"(b[0]), "r"(b[1]));
}

// ============================================================================
// prep: wnorm, wmax, fp32 transpose, swizzled bf16 transpose, zero accums
// ============================================================================
__global__ void prep_kernel(const float* __restrict__ W) {
    int e = blockIdx.x * blockDim.x + threadIdx.x;
    if (blockIdx.x == 0 && threadIdx.x == 0) { g_loss = 0.0; g_nfb = 0; }
    if (e >= NEMB) return;
    float col[DIMS];
    float s = 0.f;
    #pragma unroll
    for (int d = 0; d < DIMS; ++d) {
        float v = W[d * NEMB + e];
        col[d] = v;
        s = fmaf(v, v, s);
    }
    g_wnorm[e] = s;
    atomicMax(&g_wmaxbits, __float_as_int(s));   // s > 0 -> int-bit max valid
    float4* dst = (float4*)(g_Wtf + (size_t)e * DIMS);
    #pragma unroll
    for (int i = 0; i < DIMS / 4; ++i)
        dst[i] = make_float4(col[4*i], col[4*i+1], col[4*i+2], col[4*i+3]);
    char* bb = (char*)g_Wtb;
    #pragma unroll
    for (int k = 0; k < DIMS; k += 2) {
        __nv_bfloat162 p = __floats2bfloat162_rn(col[k], col[k + 1]);
        uint32_t bo = (uint32_t)e * 128u + (uint32_t)k * 2u;
        *(uint32_t*)(bb + sw128(bo)) = *(uint32_t*)&p;
    }
}

// ============================================================================
// vq: 512 rows/CTA, 16 warps. Two MMA sweeps: (1) running min, (2) exact
// candidate set {e : s~ < s~min + margin} into smem slots. Then exact refine.
// ============================================================================
__global__ __launch_bounds__(TPB, 1) void vq_kernel(
    const float* __restrict__ latents,
    const float* __restrict__ scaler,
    const float* __restrict__ redshift,
    float* __restrict__ out,
    int N)
{
    extern __shared__ char smem[];
    const uint32_t sb = smem_u32(smem);
    const int tid = threadIdx.x, wid = tid >> 5, lane = tid & 31;
    const long long row0 = (long long)blockIdx.x * MTILE;

    float* swn  = (float*)(smem + SM_WN);
    float* szn  = (float*)(smem + SM_ZN);
    int*   scand = (int*)(smem + SM_CAND);
    int*   scnt  = (int*)(smem + SM_CNT);

    // ---- prologue fills ----
    for (int i = tid; i < MTILE; i += TPB) scnt[i] = 0;
    {
        const float4* src = (const float4*)g_Wtb;
        float4* dst = (float4*)(smem + SM_B);
        #pragma unroll 8
        for (int i = tid; i < NEMB * 128 / 16; i += TPB) dst[i] = src[i];
    }
    for (int i = tid; i < NEMB; i += TPB) swn[i] = g_wnorm[i];
    // A convert (f32 -> bf16 swizzled) + per-row ||z||^2 (warp-uniform row)
    for (int i = tid; i < MTILE * 32; i += TPB) {
        int r = i >> 5, kp = i & 31;          // whole warp shares r
        long long gr = row0 + r;
        float2 z2 = (gr < N) ? ((const float2*)latents)[gr * 32 + kp]
                             : make_float2(0.f, 0.f);
        __nv_bfloat162 p = __floats2bfloat162_rn(z2.x, z2.y);
        *(uint32_t*)(smem + SM_A + sw128((uint32_t)r * 128u + (uint32_t)kp * 4u))
            = *(uint32_t*)&p;
        float zp = fmaf(z2.x, z2.x, z2.y * z2.y);
        #pragma unroll
        for (int o = 16; o > 0; o >>= 1)
            zp += __shfl_down_sync(0xffffffffu, zp, o);
        if (lane == 0) szn[r] = zp;
    }
    __syncthreads();

    // ---- A fragments (register resident): 2 m16 tiles x 4 k16 steps
    const int wb = wid * 32;
    uint32_t afrag[2][4][4];
    {
        int row = wb + ((lane >> 3) & 1) * 8 + (lane & 7);
        #pragma unroll
        for (int mt = 0; mt < 2; ++mt) {
            int rr = row + mt * 16;
            #pragma unroll
            for (int ks = 0; ks < 4; ++ks) {
                int kb = ks * 2 + (lane >> 4);
                uint32_t ad = sb + SM_A + rr * 128 + ((kb ^ (rr & 7)) << 4);
                LDSM_X4(afrag[mt][ks], ad);
            }
        }
    }

    const uint32_t brow = sb + SM_B + (lane & 7) * 128;
    const uint32_t bx1  = (((lane >> 3) ^ (lane & 7)) << 4);
    const uint32_t bx2  = ((((lane >> 3) + 4) ^ (lane & 7)) << 4);
    const int cbase = (lane & 3) * 2;

    // ================= pass 1: running min per state (branchless) ===========
    float m0 = 3.402823466e38f, m1 = m0, m2 = m0, m3 = m0;
    #pragma unroll 2
    for (int nt = 0; nt < NEMB / 8; ++nt) {
        const int n0 = nt * 8;
        uint32_t b[8];
        LDSM_X4(b,     brow + n0 * 128 + bx1);
        LDSM_X4(b + 4, brow + n0 * 128 + bx2);
        float d0[4] = {0.f, 0.f, 0.f, 0.f};
        float d1[4] = {0.f, 0.f, 0.f, 0.f};
        #pragma unroll
        for (int ks = 0; ks < 4; ++ks) {
            mma16816(d0, afrag[0][ks], b + 2 * ks);
            mma16816(d1, afrag[1][ks], b + 2 * ks);
        }
        const float wn0 = swn[n0 + cbase], wn1 = swn[n0 + cbase + 1];
        m0 = fminf(m0, fmaf(d0[0], -2.f, wn0));
        m0 = fminf(m0, fmaf(d0[1], -2.f, wn1));
        m1 = fminf(m1, fmaf(d0[2], -2.f, wn0));
        m1 = fminf(m1, fmaf(d0[3], -2.f, wn1));
        m2 = fminf(m2, fmaf(d1[0], -2.f, wn0));
        m2 = fminf(m2, fmaf(d1[1], -2.f, wn1));
        m3 = fminf(m3, fmaf(d1[2], -2.f, wn0));
        m3 = fminf(m3, fmaf(d1[3], -2.f, wn1));
    }
    // quad merge (cols of a row live in lanes sharing lane>>2)
    m0 = fminf(m0, __shfl_xor_sync(0xffffffffu, m0, 1));
    m0 = fminf(m0, __shfl_xor_sync(0xffffffffu, m0, 2));
    m1 = fminf(m1, __shfl_xor_sync(0xffffffffu, m1, 1));
    m1 = fminf(m1, __shfl_xor_sync(0xffffffffu, m1, 2));
    m2 = fminf(m2, __shfl_xor_sync(0xffffffffu, m2, 1));
    m2 = fminf(m2, __shfl_xor_sync(0xffffffffu, m2, 2));
    m3 = fminf(m3, __shfl_xor_sync(0xffffffffu, m3, 1));
    m3 = fminf(m3, __shfl_xor_sync(0xffffffffu, m3, 2));

    // thresholds: rigorous bf16 completeness margin 2eps = 2^-5*||z||*max||w||
    const float wmax = __int_as_float(g_wmaxbits);
    const int rl0 = wb + (lane >> 2);
    const int rl1 = rl0 + 8, rl2 = rl0 + 16, rl3 = rl0 + 24;
    const float t0 = m0 + 0.03125f * sqrtf(szn[rl0] * wmax) + 1e-4f;
    const float t1 = m1 + 0.03125f * sqrtf(szn[rl1] * wmax) + 1e-4f;
    const float t2 = m2 + 0.03125f * sqrtf(szn[rl2] * wmax) + 1e-4f;
    const float t3 = m3 + 0.03125f * sqrtf(szn[rl3] * wmax) + 1e-4f;

    // ================= pass 2: exact candidate collection ===================
#define PUSH(RL, E) do {                                                      \
        int _s = atomicAdd(&scnt[RL], 1);                                     \
        if (_s < NSLOT) scand[(RL) * NSLOT + _s] = (E);                       \
    } while (0)

    #pragma unroll 2
    for (int nt = 0; nt < NEMB / 8; ++nt) {
        const int n0 = nt * 8;
        uint32_t b[8];
        LDSM_X4(b,     brow + n0 * 128 + bx1);
        LDSM_X4(b + 4, brow + n0 * 128 + bx2);
        float d0[4] = {0.f, 0.f, 0.f, 0.f};
        float d1[4] = {0.f, 0.f, 0.f, 0.f};
        #pragma unroll
        for (int ks = 0; ks < 4; ++ks) {
            mma16816(d0, afrag[0][ks], b + 2 * ks);
            mma16816(d1, afrag[1][ks], b + 2 * ks);
        }
        const int c0 = n0 + cbase, c1 = c0 + 1;
        const float wn0 = swn[c0], wn1 = swn[c1];
        float s;
        s = fmaf(d0[0], -2.f, wn0); if (s < t0) PUSH(rl0, c0);
        s = fmaf(d0[1], -2.f, wn1); if (s < t0) PUSH(rl0, c1);
        s = fmaf(d0[2], -2.f, wn0); if (s < t1) PUSH(rl1, c0);
        s = fmaf(d0[3], -2.f, wn1); if (s < t1) PUSH(rl1, c1);
        s = fmaf(d1[0], -2.f, wn0); if (s < t2) PUSH(rl2, c0);
        s = fmaf(d1[1], -2.f, wn1); if (s < t2) PUSH(rl2, c1);
        s = fmaf(d1[2], -2.f, wn0); if (s < t3) PUSH(rl3, c0);
        s = fmaf(d1[3], -2.f, wn1); if (s < t3) PUSH(rl3, c1);
    }
#undef PUSH
    __syncthreads();

    // ================= exact fp32 refine + epilogue (1 row / thread) ========
    const int rl = tid;
    const long long r = row0 + rl;
    float lsum = 0.f;
    if (r < N) {
        const int cnt = scnt[rl];
        if (cnt > NSLOT) {
            int ix = atomicAdd(&g_nfb, 1);
            if (ix < FB_CAP) g_fbrows[ix] = (int)r;
        } else {
            const float4* zr = (const float4*)(latents + r * DIMS);
            float4 z[DIMS / 4];
            float zn = 0.f;
            #pragma unroll
            for (int i = 0; i < DIMS / 4; ++i) {
                z[i] = zr[i];
                zn = fmaf(z[i].x, z[i].x, zn); zn = fmaf(z[i].y, z[i].y, zn);
                zn = fmaf(z[i].z, z[i].z, zn); zn = fmaf(z[i].w, z[i].w, zn);
            }
            float bd = 3.402823466e38f; int be = NEMB;
            for (int c = 0; c < cnt; ++c) {
                const int ie = scand[rl * NSLOT + c];
                const float4* wp = (const float4*)(g_Wtf + (size_t)ie * DIMS);
                float a = 0.f;
                #pragma unroll
                for (int i = 0; i < DIMS / 4; ++i) {
                    float4 p = wp[i];
                    a = fmaf(z[i].x, p.x, a); a = fmaf(z[i].y, p.y, a);
                    a = fmaf(z[i].z, p.z, a); a = fmaf(z[i].w, p.w, a);
                }
                float d = (zn - 2.f * a) + swn[ie];   // exact reference order
                if (d < bd || (d == bd && ie < be)) { bd = d; be = ie; }
            }
            const float4* wq = (const float4*)(g_Wtf + (size_t)be * DIMS);
            float4* oz = (float4*)(out + r * DIMS);
            #pragma unroll
            for (int i = 0; i < DIMS / 4; ++i) {
                float4 w = wq[i];
                float q0 = w.x - z[i].x, q1 = w.y - z[i].y;
                float q2 = w.z - z[i].z, q3 = w.w - z[i].w;
                lsum += q0*q0 + q1*q1 + q2*q2 + q3*q3;
                oz[i] = make_float4(z[i].x + q0, z[i].y + q1,
                                    z[i].z + q2, z[i].w + q3);
            }
            out[(long long)N * DIMS + 2LL * N + 1 + r] = (float)be;
        }
        out[(long long)N * DIMS + r]     = scaler[r];
        out[(long long)N * DIMS + N + r] = redshift[r];
    }

    // ---- block loss reduction
    #pragma unroll
    for (int o = 16; o > 0; o >>= 1)
        lsum += __shfl_down_sync(0xffffffffu, lsum, o);
    float* wsum = (float*)(smem + SM_WSUM);
    if (lane == 0) wsum[wid] = lsum;
    __syncthreads();
    if (tid == 0) {
        float t = 0.f;
        #pragma unroll
        for (int w = 0; w < TPB / 32; ++w) t += wsum[w];
        atomicAdd(&g_loss, (double)t);
    }
}

// ============================================================================
// fallback: exact fp32 full scan (one warp per row); expected ~0 rows
// ============================================================================
__global__ void fb_kernel(const float* __restrict__ latents,
                          float* __restrict__ out, int N)
{
    __shared__ float zbuf[4][DIMS];
    const int lane = threadIdx.x & 31, w = threadIdx.x >> 5;
    const int warps = (gridDim.x * blockDim.x) >> 5;
    const int gw = (blockIdx.x * blockDim.x + threadIdx.x) >> 5;
    const int nfb = min(g_nfb, FB_CAP);

    for (int i = gw; i < nfb; i += warps) {
        const long long row = g_fbrows[i];
        zbuf[w][2*lane]     = latents[row * DIMS + 2*lane];
        zbuf[w][2*lane + 1] = latents[row * DIMS + 2*lane + 1];
        __syncwarp();
        float zp = zbuf[w][2*lane] * zbuf[w][2*lane]
                 + zbuf[w][2*lane+1] * zbuf[w][2*lane+1];
        #pragma unroll
        for (int o = 16; o > 0; o >>= 1) zp += __shfl_down_sync(0xffffffffu, zp, o);
        float zn = __shfl_sync(0xffffffffu, zp, 0);

        const float4* z4 = (const float4*)zbuf[w];
        float bd = 3.4e38f; int be = NEMB;
        for (int e = lane; e < NEMB; e += 32) {
            const float4* wp = (const float4*)(g_Wtf + (size_t)e * DIMS);
            float a = 0.f;
            #pragma unroll
            for (int k = 0; k < DIMS / 4; ++k) {
                float4 zv = z4[k], p = wp[k];
                a = fmaf(zv.x,p.x,a); a = fmaf(zv.y,p.y,a);
                a = fmaf(zv.z,p.z,a); a = fmaf(zv.w,p.w,a);
            }
            float d = (zn - 2.f * a) + g_wnorm[e];
            if (d < bd || (d == bd && e < be)) { bd = d; be = e; }
        }
        #pragma unroll
        for (int o = 16; o > 0; o >>= 1) {
            float od = __shfl_down_sync(0xffffffffu, bd, o);
            int   oe = __shfl_down_sync(0xffffffffu, be, o);
            if (od < bd || (od == bd && oe < be)) { bd = od; be = oe; }
        }
        be = __shfl_sync(0xffffffffu, be, 0);

        float l = 0.f;
        #pragma unroll
        for (int k = 0; k < 2; ++k) {
            int d = 2*lane + k;
            float zv = zbuf[w][d];
            float wv = g_Wtf[(size_t)be * DIMS + d];
            float df = wv - zv;
            l += df * df;
            out[row * DIMS + d] = zv + df;
        }
        #pragma unroll
        for (int o = 16; o > 0; o >>= 1) l += __shfl_down_sync(0xffffffffu, l, o);
        if (lane == 0) {
            atomicAdd(&g_loss, (double)l);
            out[(long long)N * DIMS + 2LL * N + 1 + row] = (float)be;
        }
        __syncwarp();
    }
}

__global__ void finalize_kernel(float* __restrict__ out, long long off, double scale) {
    out[off] = (float)(g_loss * scale);
}

// ============================================================================
extern "C" void kernel_launch(void* const* d_in, const int* in_sizes, int n_in,
                              void* d_out, int out_size) {
    const float* latents  = (const float*)d_in[0];
    const float* scaler   = (const float*)d_in[1];
    const float* redshift = (const float*)d_in[2];
    const float* W        = (const float*)d_in[3];
    float* out = (float*)d_out;
    const int N = in_sizes[1];

    cudaFuncSetAttribute(vq_kernel, cudaFuncAttributeMaxDynamicSharedMemorySize,
                         SM_TOTAL);

    prep_kernel<<<(NEMB + 255) / 256, 256>>>(W);
    vq_kernel<<<(N + MTILE - 1) / MTILE, TPB, SM_TOTAL>>>(latents, scaler,
                                                          redshift, out, N);
    fb_kernel<<<128, 128>>>(latents, out, N);
    finalize_kernel<<<1, 1>>>(out, (long long)N * DIMS + 2LL * N,
                              1.25 / ((double)N * (double)DIMS));
}